// round 10
// baseline (speedup 1.0000x reference)
#include <cuda_runtime.h>
#include <cuda_fp16.h>
#include <math.h>
#include <stdint.h>

// ===========================================================================
#define N_VEC   65536
#define DIM     256
#define KCODES  2048
#define CAP     12          // candidate cap per row

#define OFF_LOSS  0
#define OFF_QUANT 1
#define OFF_PERP  (1 + 64*256*32*32)
#define OFF_IDX   (OFF_PERP + 1)

// ===========================================================================
__device__ __forceinline__ uint32_t smem_to_u32(const void* p) {
    uint32_t a;
    asm("{ .reg .u64 t; cvta.to.shared.u64 t, %1; cvt.u32.u64 %0, t; }" : "=r"(a) : "l"(p));
    return a;
}
#define MBARRIER_INIT(mbar, cnt) \
    asm volatile("mbarrier.init.shared.b64 [%0], %1;" :: "r"((uint32_t)(mbar)), "r"((uint32_t)(cnt)) : "memory")
#define MBARRIER_EXPECT_TX(mbar, bytes) \
    asm volatile("mbarrier.arrive.expect_tx.shared.b64 _, [%0], %1;" \
        :: "r"((uint32_t)(mbar)), "r"((uint32_t)(bytes)) : "memory")
#define MBARRIER_WAIT_PARITY(mbar_addr, parity) do { \
    uint32_t _mbar = (uint32_t)(mbar_addr); \
    uint32_t _par = (uint32_t)(parity); \
    uint32_t _done; \
    asm volatile("{\n\t.reg .pred p;\n\t" \
        "mbarrier.try_wait.parity.acquire.cta.shared::cta.b64 p, [%1], %2;\n\t" \
        "selp.b32 %0, 1, 0, p;\n\t}" : "=r"(_done) : "r"(_mbar), "r"(_par) : "memory"); \
    if (!_done) { \
        asm volatile("{\n\t.reg .pred P1;\n\t" \
            "WL_%=:\n\t" \
            "mbarrier.try_wait.parity.acquire.cta.shared::cta.b64 P1, [%0], %1, 0x989680;\n\t" \
            "@P1 bra.uni WD_%=;\n\t" \
            "bra.uni WL_%=;\n\t" \
            "WD_%=:\n\t}" :: "r"(_mbar), "r"(_par) : "memory"); \
    } \
} while (0)
#define TMA_BULK_G2S(dst_smem, src_gmem, nbytes, mbar) \
    asm volatile("cp.async.bulk.shared::cluster.global.mbarrier::complete_tx::bytes [%0], [%1], %2, [%3];" \
        :: "r"((uint32_t)(dst_smem)), "l"(src_gmem), "r"((uint32_t)(nbytes)), "r"((uint32_t)(mbar)) : "memory")

#define LDM_X4(r0, r1, r2, r3, addr) \
    asm volatile("ldmatrix.sync.aligned.m8n8.x4.shared.b16 {%0,%1,%2,%3}, [%4];" \
        : "=r"(r0), "=r"(r1), "=r"(r2), "=r"(r3) : "r"(addr))
#define LDM_X4T(r0, r1, r2, r3, addr) \
    asm volatile("ldmatrix.sync.aligned.m8n8.x4.trans.shared.b16 {%0,%1,%2,%3}, [%4];" \
        : "=r"(r0), "=r"(r1), "=r"(r2), "=r"(r3) : "r"(addr))
#define MMA_F16(d, a0, a1, a2, a3, b0, b1) \
    asm volatile("mma.sync.aligned.m16n8k16.row.col.f32.f16.f16.f32 " \
        "{%0,%1,%2,%3}, {%4,%5,%6,%7}, {%8,%9}, {%0,%1,%2,%3};" \
        : "+f"((d)[0]), "+f"((d)[1]), "+f"((d)[2]), "+f"((d)[3]) \
        : "r"(a0), "r"(a1), "r"(a2), "r"(a3), "r"(b0), "r"(b1))

// ===========================================================================
// B image: per stage block s = tile*4+kc of 18432 B = 128 codes x (128B + 16B pad).
#define B_ROW_B   144
#define B_ROW_E   72
#define B_BLOCK_E (128 * B_ROW_E)   // 9216 halfs per block
__device__ __half g_cbHP[64 * B_BLOCK_E];     // fp16(c * 4096), padded
__device__ float g_csq[KCODES];
__device__ float g_cmax;                       // max_k ||c_k||
__device__ float g_xsq[N_VEC];
__device__ int   g_cand[N_VEC * CAP];
__device__ int   g_ccnt[N_VEC];
__device__ int   g_idx[N_VEC];
__device__ unsigned long long g_sse;
__device__ int   g_cnt[KCODES];

// ===========================================================================
__global__ void k_init()
{
    int t = blockIdx.x * 256 + threadIdx.x;
    if (t == 0) g_sse = 0ULL;
    if (t < KCODES) g_cnt[t] = 0;
}

// fp16 split (x4096 exact scale) + csq
__global__ void k_split(const float* __restrict__ cb)
{
    __shared__ float red[256];
    int code = blockIdx.x, d = threadIdx.x;
    float x = cb[code * DIM + d];
    int tile = code >> 7, r = code & 127, kc = d >> 6, j = d & 63;
    g_cbHP[(size_t)(tile * 4 + kc) * B_BLOCK_E + r * B_ROW_E + j] =
        __float2half_rn(x * 4096.0f);
    red[d] = x * x;
    __syncthreads();
    for (int m = 128; m; m >>= 1) {
        if (d < m) red[d] += red[d + m];
        __syncthreads();
    }
    if (d == 0) g_csq[code] = red[0];
}

__global__ void k_cmax()
{
    __shared__ float red[256];
    int tid = threadIdx.x;
    float m = 0.f;
    for (int k = tid; k < KCODES; k += 256) m = fmaxf(m, g_csq[k]);
    red[tid] = m;
    __syncthreads();
    for (int s = 128; s; s >>= 1) {
        if (tid < s) red[tid] = fmaxf(red[tid], red[tid + s]);
        __syncthreads();
    }
    if (tid == 0) g_cmax = sqrtf(red[0]);
}

// ===========================================================================
// Phase 1: fp16 hi*hi mma.sync GEMM + certified candidate collection.
#define AT_STRIDE_B 272
#define A_TOTAL_B   (256 * AT_STRIDE_B)       // 69632
#define B_STG_B     18432
#define B_OFF       A_TOTAL_B                 // 69632
#define CAND_OFF    (B_OFF + 2 * B_STG_B)     // 106496
#define CNT_OFF     (CAND_OFF + 128 * CAP * 4)// 112640
#define S1_OFF      (CNT_OFF + 512)           // 113152
#define SB_OFF      (S1_OFF + 512)            // 113664
#define MB_OFF      (SB_OFF + 512)            // 114176
#define P1_SMEM     (MB_OFF + 64)             // 114240 (111.6 KB -> 2 CTAs/SM)
#define INV2048F    4.8828125e-4f

__global__ __launch_bounds__(256, 2)
void k_phase1(const float* __restrict__ inp)
{
    extern __shared__ __align__(128) char smem[];
    uint32_t su = smem_to_u32(smem);
    int tid = threadIdx.x, w = tid >> 5, lane = tid & 31;
    int row0 = blockIdx.x * 128;
    int b = row0 >> 10, rem0 = row0 & 1023;

    int*   scnt = (int*)(smem + CNT_OFF);
    int*   sBI  = (int*)(smem + SB_OFF);
    int*   scand = (int*)(smem + CAND_OFF);

    if (tid == 0) {
        MBARRIER_INIT(su + MB_OFF,     1);
        MBARRIER_INIT(su + MB_OFF + 8, 1);
    }
    if (tid < 128) { sBI[tid] = 0x7F7F7F7F; scnt[tid] = 0; }
    __syncthreads();
    const char* hiP = (const char*)g_cbHP;
    if (tid == 0) {
        MBARRIER_EXPECT_TX(su + MB_OFF, B_STG_B);
        TMA_BULK_G2S(su + B_OFF, hiP, B_STG_B, su + MB_OFF);
    }

    // A convert (fp16, K-major) + fused ||x||^2 partials (R8-validated scheme)
    {
        const float* srcb = inp + (size_t)b * 262144 + rem0;
        int kb = tid >> 4, rb = tid & 15;
        float pacc[8];
#pragma unroll
        for (int j = 0; j < 8; ++j) pacc[j] = 0.f;
#pragma unroll 2
        for (int i = 0; i < 16; ++i) {
            int k = kb + (i << 4);
            const float4* p = (const float4*)(srcb + (size_t)k * 1024 + rb * 8);
            float4 v0 = __ldg(p), v1 = __ldg(p + 1);
            float xv[8] = {v0.x, v0.y, v0.z, v0.w, v1.x, v1.y, v1.z, v1.w};
            uint32_t hp[4];
#pragma unroll
            for (int q = 0; q < 4; ++q) {
                float a0 = xv[2 * q], a1 = xv[2 * q + 1];
                __half2 h2 = __floats2half2_rn(a0, a1);
                hp[q] = *(uint32_t*)&h2;
                pacc[2 * q]     = fmaf(a0, a0, pacc[2 * q]);
                pacc[2 * q + 1] = fmaf(a1, a1, pacc[2 * q + 1]);
            }
            *(uint4*)(smem + k * AT_STRIDE_B + rb * 16) = make_uint4(hp[0], hp[1], hp[2], hp[3]);
        }
        float* part = (float*)(smem + B_OFF + B_STG_B);  // buf1, free until stage 1
#pragma unroll
        for (int j = 0; j < 8; ++j) part[kb * 128 + rb * 8 + j] = pacc[j];
    }
    __syncthreads();
    if (tid < 128) {
        const float* part = (const float*)(smem + B_OFF + B_STG_B);
        float s = 0.f;
#pragma unroll
        for (int g = 0; g < 16; ++g) s += part[g * 128 + tid];   // fixed order
        ((float*)(smem + S1_OFF))[tid] = s;
        g_xsq[row0 + tid] = s;
    }
    __syncthreads();

    uint32_t aBase = su + ((lane & 7) + ((lane & 16) >> 1)) * AT_STRIDE_B
                   + (uint32_t)(w * 16 + ((lane & 8) ? 8 : 0)) * 2u;
    uint32_t bOff = (uint32_t)((lane & 7) + ((lane & 16) ? 8 : 0)) * B_ROW_B
                  + (uint32_t)((lane & 8) ? 16 : 0);

    const float* s1s = (const float*)(smem + S1_OFF);
    int rloc = w * 16 + (lane >> 2);
    float s1r0 = s1s[rloc], s1r1 = s1s[rloc + 8];
    float cmax = g_cmax;
    // certified collection window (fp16 half-ulp bound + margin)
    float eps0 = sqrtf(s1r0) * (5.2e-3f * cmax + 3e-6f) + 3e-4f;
    float eps1 = sqrtf(s1r1) * (5.2e-3f * cmax + 3e-6f) + 3e-4f;

    float acc[64];

    for (int s = 0; s < 64; ++s) {
        int kc = s & 3;
        if (s + 1 < 64 && tid == 0) {
            uint32_t mb  = su + MB_OFF + (uint32_t)((s + 1) & 1) * 8u;
            uint32_t dst = su + B_OFF + (uint32_t)((s + 1) & 1) * B_STG_B;
            MBARRIER_EXPECT_TX(mb, B_STG_B);
            TMA_BULK_G2S(dst, hiP + (size_t)(s + 1) * B_STG_B, B_STG_B, mb);
        }
        MBARRIER_WAIT_PARITY(su + MB_OFF + (s & 1) * 8, (s >> 1) & 1);

        if (kc == 0) {
#pragma unroll
            for (int i = 0; i < 64; ++i) acc[i] = 0.f;
        }
        uint32_t Bst = su + B_OFF + (uint32_t)(s & 1) * B_STG_B + bOff;

#pragma unroll
        for (int ks2 = 0; ks2 < 4; ++ks2) {
            int ks = kc * 4 + ks2;
            uint32_t ah[4];
            LDM_X4T(ah[0], ah[1], ah[2], ah[3], aBase + (uint32_t)ks * (16u * AT_STRIDE_B));
#pragma unroll
            for (int tp = 0; tp < 8; ++tp) {
                uint32_t bh[4];
                LDM_X4(bh[0], bh[1], bh[2], bh[3],
                       Bst + (uint32_t)tp * (16u * B_ROW_B) + (uint32_t)ks2 * 32u);
                MMA_F16(&acc[(tp * 2 + 0) * 4], ah[0], ah[1], ah[2], ah[3], bh[0], bh[1]);
                MMA_F16(&acc[(tp * 2 + 1) * 4], ah[0], ah[1], ah[2], ah[3], bh[2], bh[3]);
            }
        }

        if (kc == 3) {
            int codeBase = (s >> 2) * 128;
            // pass A: per-row running best (smem atomicMin on positive floats)
            float mn0 = 3.4e38f, mn1 = 3.4e38f;
#pragma unroll
            for (int t = 0; t < 16; ++t) {
                int c0 = codeBase + t * 8 + 2 * (lane & 3);
                float2 cs2 = __ldg((const float2*)&g_csq[c0]);
                mn0 = fminf(mn0, __fsub_rn(__fadd_rn(s1r0, cs2.x), acc[t * 4 + 0] * INV2048F));
                mn0 = fminf(mn0, __fsub_rn(__fadd_rn(s1r0, cs2.y), acc[t * 4 + 1] * INV2048F));
                mn1 = fminf(mn1, __fsub_rn(__fadd_rn(s1r1, cs2.x), acc[t * 4 + 2] * INV2048F));
                mn1 = fminf(mn1, __fsub_rn(__fadd_rn(s1r1, cs2.y), acc[t * 4 + 3] * INV2048F));
            }
            atomicMin(&sBI[rloc],     __float_as_int(mn0));
            atomicMin(&sBI[rloc + 8], __float_as_int(mn1));
            __syncthreads();
            // pass B: collect within certified window of the (tight) running best
            float th0 = __int_as_float(sBI[rloc]) + eps0;
            float th1 = __int_as_float(sBI[rloc + 8]) + eps1;
#pragma unroll
            for (int t = 0; t < 16; ++t) {
                int c0 = codeBase + t * 8 + 2 * (lane & 3);
                float2 cs2 = __ldg((const float2*)&g_csq[c0]);
                float d00 = __fsub_rn(__fadd_rn(s1r0, cs2.x), acc[t * 4 + 0] * INV2048F);
                float d01 = __fsub_rn(__fadd_rn(s1r0, cs2.y), acc[t * 4 + 1] * INV2048F);
                float d10 = __fsub_rn(__fadd_rn(s1r1, cs2.x), acc[t * 4 + 2] * INV2048F);
                float d11 = __fsub_rn(__fadd_rn(s1r1, cs2.y), acc[t * 4 + 3] * INV2048F);
                if (d00 < th0) { int p = atomicAdd(&scnt[rloc], 1);     if (p < CAP) scand[rloc * CAP + p] = c0; }
                if (d01 < th0) { int p = atomicAdd(&scnt[rloc], 1);     if (p < CAP) scand[rloc * CAP + p] = c0 + 1; }
                if (d10 < th1) { int p = atomicAdd(&scnt[rloc + 8], 1); if (p < CAP) scand[(rloc + 8) * CAP + p] = c0; }
                if (d11 < th1) { int p = atomicAdd(&scnt[rloc + 8], 1); if (p < CAP) scand[(rloc + 8) * CAP + p] = c0 + 1; }
            }
        }
        __syncthreads();
    }

    if (tid < 128) g_ccnt[row0 + tid] = scnt[tid];
    for (int i = tid; i < 128 * CAP; i += 256)
        g_cand[(size_t)(row0 + i / CAP) * CAP + (i % CAP)] = scand[i];
}

// ===========================================================================
// Phase 2 fused: exact fp32 recheck of candidates -> idx, then gather/quant/SSE.
__global__ __launch_bounds__(256)
void k_finalize(const float* __restrict__ inp, const float* __restrict__ cb,
                float* __restrict__ out)
{
    __shared__ float xr[256];
    __shared__ float sv[256];
    __shared__ int   si[256];
    __shared__ int   ovf_rows[256];
    __shared__ int   ovf_n;

    int tid = threadIdx.x;
    int row = blockIdx.x * 256 + tid;
    int b = row >> 10, rem = row & 1023;
    size_t base = (size_t)b * 262144 + rem;
    int cnt = g_ccnt[row];
    float s1 = g_xsq[row];

    if (tid == 0) ovf_n = 0;
    __syncthreads();

    // lockstep candidate recheck (exact fp32 serial, d ascending — R3 class)
    int cc = cnt < CAP ? cnt : CAP;
    int wmax = cc;
#pragma unroll
    for (int m = 16; m; m >>= 1) {
        int o = __shfl_xor_sync(0xffffffffu, wmax, m);
        wmax = o > wmax ? o : wmax;
    }
    float best = 3.4e38f; int bi = 0;
    for (int i = 0; i < wmax; ++i) {
        int ci = g_cand[(size_t)row * CAP + (i < cc ? i : 0)];
        const float4* cr = (const float4*)(cb + (size_t)ci * DIM);
        float m = 0.f;
#pragma unroll 4
        for (int d4 = 0; d4 < 64; ++d4) {
            float4 cv = __ldg(cr + d4);
            m = fmaf(inp[base + (size_t)(d4 * 4 + 0) * 1024], cv.x, m);
            m = fmaf(inp[base + (size_t)(d4 * 4 + 1) * 1024], cv.y, m);
            m = fmaf(inp[base + (size_t)(d4 * 4 + 2) * 1024], cv.z, m);
            m = fmaf(inp[base + (size_t)(d4 * 4 + 3) * 1024], cv.w, m);
        }
        if (i < cc) {
            float dd = __fsub_rn(__fadd_rn(s1, g_csq[ci]), 2.0f * m);
            if (dd < best || (dd == best && ci < bi)) { best = dd; bi = ci; }
        }
    }

    // block-cooperative fallback for overflow rows (provably rare)
    if (cnt > CAP) { int p = atomicAdd(&ovf_n, 1); ovf_rows[p] = tid; }
    __syncthreads();
    for (int k = 0; k < ovf_n; ++k) {
        int rt_ = ovf_rows[k];
        int orow = blockIdx.x * 256 + rt_;
        int ob = orow >> 10, orem = orow & 1023;
        xr[tid] = inp[(size_t)ob * 262144 + (size_t)tid * 1024 + orem];
        __syncthreads();
        float os1 = g_xsq[orow];
        float v = 3.4e38f; int vi = 0;
        for (int c = tid; c < KCODES; c += 256) {
            const float* cr = cb + (size_t)c * DIM;
            float m = 0.f;
#pragma unroll 8
            for (int d = 0; d < DIM; ++d) m = fmaf(xr[d], __ldg(cr + d), m);
            float dd = __fsub_rn(__fadd_rn(os1, g_csq[c]), 2.0f * m);
            if (dd < v || (dd == v && c < vi)) { v = dd; vi = c; }
        }
        sv[tid] = v; si[tid] = vi;
        __syncthreads();
        for (int m2 = 128; m2; m2 >>= 1) {
            if (tid < m2) {
                if (sv[tid + m2] < sv[tid] ||
                    (sv[tid + m2] == sv[tid] && si[tid + m2] < si[tid])) {
                    sv[tid] = sv[tid + m2]; si[tid] = si[tid + m2];
                }
            }
            __syncthreads();
        }
        if (tid == rt_) { best = sv[0]; bi = si[0]; }
        __syncthreads();
    }

    g_idx[row] = bi;
    out[OFF_IDX + row] = (float)bi;

    // gather / quant / SSE  (float4 codebook reads, coalesced x/quant)
    {
        const float4* cr = (const float4*)(cb + (size_t)bi * DIM);
        float s = 0.f;
#pragma unroll 4
        for (int d4 = 0; d4 < 64; ++d4) {
            float4 cv = __ldg(cr + d4);
            float qv[4] = {cv.x, cv.y, cv.z, cv.w};
#pragma unroll
            for (int j = 0; j < 4; ++j) {
                size_t off = base + (size_t)(d4 * 4 + j) * 1024;
                float x = inp[off];
                out[OFF_QUANT + off] = __fadd_rn(x, __fsub_rn(qv[j], x));
                float df = __fsub_rn(qv[j], x);
                s = fmaf(df, df, s);
            }
        }
        sv[tid] = s;
        __syncthreads();
        for (int m2 = 128; m2; m2 >>= 1) {
            if (tid < m2) sv[tid] += sv[tid + m2];
            __syncthreads();
        }
        if (tid == 0) {
            double v = (double)sv[0] * 256.0;
            atomicAdd(&g_sse, (unsigned long long)(v + 0.5));
        }
    }
}

// ===========================================================================
__global__ void k_hist()
{
    __shared__ int h[KCODES];
    for (int i = threadIdx.x; i < KCODES; i += 256) h[i] = 0;
    __syncthreads();
    for (int i = blockIdx.x * 256 + threadIdx.x; i < N_VEC; i += gridDim.x * 256)
        atomicAdd(&h[g_idx[i]], 1);
    __syncthreads();
    for (int i = threadIdx.x; i < KCODES; i += 256) {
        int c = h[i];
        if (c) atomicAdd(&g_cnt[i], c);
    }
}

__global__ void k_final(float* __restrict__ out)
{
    __shared__ float red[256];
    int tid = threadIdx.x;
    float s = 0.f;
    for (int k = tid; k < KCODES; k += 256) {
        float p = (float)g_cnt[k] * (1.0f / 65536.0f);
        s += p * logf(p + 1e-10f);
    }
    red[tid] = s;
    __syncthreads();
    for (int m = 128; m; m >>= 1) {
        if (tid < m) red[tid] += red[tid + m];
        __syncthreads();
    }
    if (tid == 0) {
        double sse = (double)g_sse * (1.0 / 256.0);
        out[OFF_LOSS] = (float)(1.25 * sse / 16777216.0);
        out[OFF_PERP] = expf(-red[0]);
    }
}

// ===========================================================================
extern "C" void kernel_launch(void* const* d_in, const int* in_sizes, int n_in,
                              void* d_out, int out_size)
{
    const float* inp = (const float*)d_in[0];
    const float* cb  = (const float*)d_in[1];
    float* out = (float*)d_out;

    cudaFuncSetAttribute(k_phase1, cudaFuncAttributeMaxDynamicSharedMemorySize, P1_SMEM);

    k_init<<<8, 256>>>();
    k_split<<<KCODES, 256>>>(cb);
    k_cmax<<<1, 256>>>();
    k_phase1<<<512, 256, P1_SMEM>>>(inp);
    k_finalize<<<256, 256>>>(inp, cb, out);
    k_hist<<<64, 256>>>();
    k_final<<<1, 256>>>(out);
}